// round 8
// baseline (speedup 1.0000x reference)
#include <cuda_runtime.h>
#include <cuda_fp16.h>
#include <stdint.h>

#define NMAX 50000
#define EMAX 1600000
#define SCAN_CHUNK 512

// ---------------- scratch (device globals; no allocation) ----------------
__device__ __half2 g_h2[NMAX * 32];       // h [N,64] fp16
__device__ float4  g_asrc4[NMAX];         // a_src [N,4]
__device__ float4  g_adst4[NMAX];         // a_dst [N,4]
__device__ float   g_v[64];               // v [16,4]  (d*4+h)
__device__ float   g_vsum[4];
__device__ int     g_cnt[NMAX];           // in-degree
__device__ int     g_off[NMAX];           // CSR offsets
__device__ int     g_cur[NMAX];           // write cursors
__device__ int     g_bsum[256];           // scan block sums
__device__ int4    g_rec[EMAX];           // {src, ex01(h2), ex23(h2), pad}

__device__ __forceinline__ float lrelu(float a) { return a > 0.f ? a : 0.2f * a; }

__device__ __forceinline__ unsigned h2_bits(__half2 v) {
    union { __half2 h; unsigned u; } cvt; cvt.h = v; return cvt.u;
}
__device__ __forceinline__ __half2 bits_h2(unsigned u) {
    union { unsigned u; __half2 h; } cvt; cvt.u = u; return cvt.h;
}

// ---------------- K1 (stream B): zero g_cnt; block 0 computes v/vsum -----
__global__ void k_prep(const float* __restrict__ We, const float* __restrict__ ae, int N) {
    __shared__ float sv[64];
    int g = blockIdx.x * blockDim.x + threadIdx.x;
    if (g < N) g_cnt[g] = 0;
    if (blockIdx.x == 0) {
        int t = threadIdx.x;
        if (t < 64) {
            int d = t >> 2, h = t & 3;
            float s = 0.f;
#pragma unroll
            for (int c = 0; c < 16; c++) s += We[d * 64 + h * 16 + c] * ae[h * 16 + c];
            sv[t] = s;
            g_v[t] = s;
        }
        __syncthreads();
        if (t < 4) {
            float ss = 0.f;
#pragma unroll
            for (int dd = 0; dd < 16; dd++) ss += sv[dd * 4 + t];
            g_vsum[t] = ss;
        }
    }
}

// ---------------- K2 (stream B): in-degree histogram, 8 edges/thread ------
__global__ void k_hist(const int* __restrict__ ei, int E) {
    int base = (blockIdx.x * blockDim.x + threadIdx.x) * 8;
    if (base >= E) return;
    const int* d = ei + E;
    if (base + 8 <= E && ((E & 3) == 0)) {
        int4 a = *reinterpret_cast<const int4*>(d + base);
        int4 b = *reinterpret_cast<const int4*>(d + base + 4);
        atomicAdd(&g_cnt[a.x], 1); atomicAdd(&g_cnt[a.y], 1);
        atomicAdd(&g_cnt[a.z], 1); atomicAdd(&g_cnt[a.w], 1);
        atomicAdd(&g_cnt[b.x], 1); atomicAdd(&g_cnt[b.y], 1);
        atomicAdd(&g_cnt[b.z], 1); atomicAdd(&g_cnt[b.w], 1);
    } else {
        for (int i = base; i < E && i < base + 8; i++) atomicAdd(&g_cnt[d[i]], 1);
    }
}

// ---------------- K3-5 (stream B): exclusive scan -> g_off / g_cur --------
__global__ void k_scan1(int N) {
    __shared__ int s[SCAN_CHUNK];
    int g = blockIdx.x * SCAN_CHUNK + threadIdx.x;
    int v = (g < N) ? g_cnt[g] : 0;
    s[threadIdx.x] = v;
    __syncthreads();
    for (int d = 1; d < SCAN_CHUNK; d <<= 1) {
        int tv = (threadIdx.x >= d) ? s[threadIdx.x - d] : 0;
        __syncthreads();
        s[threadIdx.x] += tv;
        __syncthreads();
    }
    if (g < N) g_off[g] = s[threadIdx.x] - v;
    if (threadIdx.x == SCAN_CHUNK - 1) g_bsum[blockIdx.x] = s[SCAN_CHUNK - 1];
}

__global__ void k_scan2(int nb) {
    __shared__ int s[256];
    int v = (threadIdx.x < nb) ? g_bsum[threadIdx.x] : 0;
    s[threadIdx.x] = v;
    __syncthreads();
    for (int d = 1; d < 256; d <<= 1) {
        int tv = (threadIdx.x >= d) ? s[threadIdx.x - d] : 0;
        __syncthreads();
        s[threadIdx.x] += tv;
        __syncthreads();
    }
    if (threadIdx.x < nb) g_bsum[threadIdx.x] = s[threadIdx.x] - v;
}

__global__ void k_scan3(int N) {
    int g = blockIdx.x * SCAN_CHUNK + threadIdx.x;
    if (g < N) {
        int o = g_off[g] + g_bsum[blockIdx.x];
        g_off[g] = o;
        g_cur[g] = o;
    }
}

// ---------------- K6 (stream A): h = x @ W, fused a_src/a_dst epilogue ----
__global__ void k_gemm(const float* __restrict__ x, const float* __restrict__ W,
                       const float* __restrict__ att_src, const float* __restrict__ att_dst,
                       int N) {
    extern __shared__ float smem[];
    float* sW = smem;             // 8192 floats
    float* sx = smem + 8192;      // 64*132 floats
    int t = threadIdx.x;
    int n0 = blockIdx.x * 64;

    for (int i = t; i < 2048; i += 256)
        reinterpret_cast<float4*>(sW)[i] = reinterpret_cast<const float4*>(W)[i];

    for (int i = t; i < 2048; i += 256) {
        int row = i >> 5;
        int col4 = i & 31;
        float4 v = make_float4(0.f, 0.f, 0.f, 0.f);
        if (n0 + row < N)
            v = reinterpret_cast<const float4*>(x)[(size_t)(n0 + row) * 32 + col4];
        float* dp = sx + row * 132 + col4 * 4;
        dp[0] = v.x; dp[1] = v.y; dp[2] = v.z; dp[3] = v.w;
    }
    __syncthreads();

    int tc = t & 15;          // channel group (4 channels)
    int tn = t >> 4;          // node group (4 nodes)
    const float* xr = sx + (tn * 4) * 132;
    float acc[4][4];
#pragma unroll
    for (int i = 0; i < 4; i++)
#pragma unroll
        for (int j = 0; j < 4; j++) acc[i][j] = 0.f;

#pragma unroll 4
    for (int k = 0; k < 128; k++) {
        float4 wv = *reinterpret_cast<const float4*>(sW + k * 64 + tc * 4);
        float x0 = xr[k], x1 = xr[132 + k], x2 = xr[264 + k], x3 = xr[396 + k];
        acc[0][0] += x0 * wv.x; acc[0][1] += x0 * wv.y; acc[0][2] += x0 * wv.z; acc[0][3] += x0 * wv.w;
        acc[1][0] += x1 * wv.x; acc[1][1] += x1 * wv.y; acc[1][2] += x1 * wv.z; acc[1][3] += x1 * wv.w;
        acc[2][0] += x2 * wv.x; acc[2][1] += x2 * wv.y; acc[2][2] += x2 * wv.z; acc[2][3] += x2 * wv.w;
        acc[3][0] += x3 * wv.x; acc[3][1] += x3 * wv.y; acc[3][2] += x3 * wv.z; acc[3][3] += x3 * wv.w;
    }

    // store h fp16
#pragma unroll
    for (int i = 0; i < 4; i++) {
        int n = n0 + tn * 4 + i;
        if (n < N) {
            __half2 p0 = __floats2half2_rn(acc[i][0], acc[i][1]);
            __half2 p1 = __floats2half2_rn(acc[i][2], acc[i][3]);
            *reinterpret_cast<uint2*>(g_h2 + n * 32 + tc * 2) =
                make_uint2(h2_bits(p0), h2_bits(p1));
        }
    }

    // fused a_src/a_dst: dot over 4 channels, reduce across 4-lane head group
    float4 asv = *reinterpret_cast<const float4*>(att_src + tc * 4);
    float4 adv = *reinterpret_cast<const float4*>(att_dst + tc * 4);
#pragma unroll
    for (int i = 0; i < 4; i++) {
        float ps = acc[i][0] * asv.x + acc[i][1] * asv.y + acc[i][2] * asv.z + acc[i][3] * asv.w;
        float pd = acc[i][0] * adv.x + acc[i][1] * adv.y + acc[i][2] * adv.z + acc[i][3] * adv.w;
        ps += __shfl_xor_sync(0xffffffffu, ps, 1);
        ps += __shfl_xor_sync(0xffffffffu, ps, 2);
        pd += __shfl_xor_sync(0xffffffffu, pd, 1);
        pd += __shfl_xor_sync(0xffffffffu, pd, 2);
        int n = n0 + tn * 4 + i;
        if ((tc & 3) == 0 && n < N) {
            int head = tc >> 2;
            ((float*)g_asrc4)[n * 4 + head] = ps;
            ((float*)g_adst4)[n * 4 + head] = pd;
        }
    }
}

// ---------------- K7: per-edge exp(lrelu(logit)) + CSR permute, 2 edges/thr
__global__ void k_edge(const int* __restrict__ ei, const float4* __restrict__ ea4, int E) {
    __shared__ float sv[64];
    if (threadIdx.x < 64) sv[threadIdx.x] = g_v[threadIdx.x];
    __syncthreads();
    int eA = blockIdx.x * 512 + threadIdx.x;
    int eB = eA + 256;
    bool vA = eA < E, vB = eB < E;

    // issue all stream loads up front (MLP 8)
    float4 qa0, qa1, qa2, qa3, qb0, qb1, qb2, qb3;
    if (vA) { qa0 = __ldcs(ea4 + eA * 4); qa1 = __ldcs(ea4 + eA * 4 + 1);
              qa2 = __ldcs(ea4 + eA * 4 + 2); qa3 = __ldcs(ea4 + eA * 4 + 3); }
    if (vB) { qb0 = __ldcs(ea4 + eB * 4); qb1 = __ldcs(ea4 + eB * 4 + 1);
              qb2 = __ldcs(ea4 + eB * 4 + 2); qb3 = __ldcs(ea4 + eB * 4 + 3); }
    int srcA = 0, dstA = 0, srcB = 0, dstB = 0;
    if (vA) { srcA = ei[eA]; dstA = ei[E + eA]; }
    if (vB) { srcB = ei[eB]; dstB = ei[E + eB]; }

    if (vA) {
        float a0, a1, a2, a3;
        {
            const float* v0 = sv, *v1 = sv + 16, *v2 = sv + 32, *v3 = sv + 48;
            a0 = qa0.x*v0[0]+qa0.y*v0[4]+qa0.z*v0[8]+qa0.w*v0[12]
               + qa1.x*v1[0]+qa1.y*v1[4]+qa1.z*v1[8]+qa1.w*v1[12]
               + qa2.x*v2[0]+qa2.y*v2[4]+qa2.z*v2[8]+qa2.w*v2[12]
               + qa3.x*v3[0]+qa3.y*v3[4]+qa3.z*v3[8]+qa3.w*v3[12];
            a1 = qa0.x*v0[1]+qa0.y*v0[5]+qa0.z*v0[9]+qa0.w*v0[13]
               + qa1.x*v1[1]+qa1.y*v1[5]+qa1.z*v1[9]+qa1.w*v1[13]
               + qa2.x*v2[1]+qa2.y*v2[5]+qa2.z*v2[9]+qa2.w*v2[13]
               + qa3.x*v3[1]+qa3.y*v3[5]+qa3.z*v3[9]+qa3.w*v3[13];
            a2 = qa0.x*v0[2]+qa0.y*v0[6]+qa0.z*v0[10]+qa0.w*v0[14]
               + qa1.x*v1[2]+qa1.y*v1[6]+qa1.z*v1[10]+qa1.w*v1[14]
               + qa2.x*v2[2]+qa2.y*v2[6]+qa2.z*v2[10]+qa2.w*v2[14]
               + qa3.x*v3[2]+qa3.y*v3[6]+qa3.z*v3[10]+qa3.w*v3[14];
            a3 = qa0.x*v0[3]+qa0.y*v0[7]+qa0.z*v0[11]+qa0.w*v0[15]
               + qa1.x*v1[3]+qa1.y*v1[7]+qa1.z*v1[11]+qa1.w*v1[15]
               + qa2.x*v2[3]+qa2.y*v2[7]+qa2.z*v2[11]+qa2.w*v2[15]
               + qa3.x*v3[3]+qa3.y*v3[7]+qa3.z*v3[11]+qa3.w*v3[15];
        }
        float4 as = g_asrc4[srcA];
        float4 ad = g_adst4[dstA];
        __half2 ex01 = __floats2half2_rn(__expf(lrelu(as.x + ad.x + a0)),
                                         __expf(lrelu(as.y + ad.y + a1)));
        __half2 ex23 = __floats2half2_rn(__expf(lrelu(as.z + ad.z + a2)),
                                         __expf(lrelu(as.w + ad.w + a3)));
        int pos = atomicAdd(&g_cur[dstA], 1);
        g_rec[pos] = make_int4(srcA, (int)h2_bits(ex01), (int)h2_bits(ex23), 0);
    }
    if (vB) {
        float a0, a1, a2, a3;
        {
            const float* v0 = sv, *v1 = sv + 16, *v2 = sv + 32, *v3 = sv + 48;
            a0 = qb0.x*v0[0]+qb0.y*v0[4]+qb0.z*v0[8]+qb0.w*v0[12]
               + qb1.x*v1[0]+qb1.y*v1[4]+qb1.z*v1[8]+qb1.w*v1[12]
               + qb2.x*v2[0]+qb2.y*v2[4]+qb2.z*v2[8]+qb2.w*v2[12]
               + qb3.x*v3[0]+qb3.y*v3[4]+qb3.z*v3[8]+qb3.w*v3[12];
            a1 = qb0.x*v0[1]+qb0.y*v0[5]+qb0.z*v0[9]+qb0.w*v0[13]
               + qb1.x*v1[1]+qb1.y*v1[5]+qb1.z*v1[9]+qb1.w*v1[13]
               + qb2.x*v2[1]+qb2.y*v2[5]+qb2.z*v2[9]+qb2.w*v2[13]
               + qb3.x*v3[1]+qb3.y*v3[5]+qb3.z*v3[9]+qb3.w*v3[13];
            a2 = qb0.x*v0[2]+qb0.y*v0[6]+qb0.z*v0[10]+qb0.w*v0[14]
               + qb1.x*v1[2]+qb1.y*v1[6]+qb1.z*v1[10]+qb1.w*v1[14]
               + qb2.x*v2[2]+qb2.y*v2[6]+qb2.z*v2[10]+qb2.w*v2[14]
               + qb3.x*v3[2]+qb3.y*v3[6]+qb3.z*v3[10]+qb3.w*v3[14];
            a3 = qb0.x*v0[3]+qb0.y*v0[7]+qb0.z*v0[11]+qb0.w*v0[15]
               + qb1.x*v1[3]+qb1.y*v1[7]+qb1.z*v1[11]+qb1.w*v1[15]
               + qb2.x*v2[3]+qb2.y*v2[7]+qb2.z*v2[11]+qb2.w*v2[15]
               + qb3.x*v3[3]+qb3.y*v3[7]+qb3.z*v3[11]+qb3.w*v3[15];
        }
        float4 as = g_asrc4[srcB];
        float4 ad = g_adst4[dstB];
        __half2 ex01 = __floats2half2_rn(__expf(lrelu(as.x + ad.x + a0)),
                                         __expf(lrelu(as.y + ad.y + a1)));
        __half2 ex23 = __floats2half2_rn(__expf(lrelu(as.z + ad.z + a2)),
                                         __expf(lrelu(as.w + ad.w + a3)));
        int pos = atomicAdd(&g_cur[dstB], 1);
        g_rec[pos] = make_int4(srcB, (int)h2_bits(ex01), (int)h2_bits(ex23), 0);
    }
}

// ---------------- K8: per-node aggregation, 2 warps per node --------------
// block = 256 (8 warps) = 4 nodes; lane owns channels {2*lane, 2*lane+1}
__global__ void k_agg(const float* __restrict__ bias, float* __restrict__ out, int N) {
    __shared__ float s_part[4][32][3];
    int warp = threadIdx.x >> 5;
    int lane = threadIdx.x & 31;
    int nb = warp >> 1;
    int half = warp & 1;
    int n = blockIdx.x * 4 + nb;
    int h = lane >> 3;

    float acc0 = 0.f, acc1 = 0.f, dn = 0.f;
    if (n < N) {
        int off = g_off[n], deg = g_cnt[n];
        int d0 = deg >> 1;
        int beg = off + (half ? d0 : 0);
        int cnt = half ? (deg - d0) : d0;

        int i = 0;
        for (; i + 4 <= cnt; i += 4) {
            int4 r0 = __ldg(g_rec + beg + i);
            int4 r1 = __ldg(g_rec + beg + i + 1);
            int4 r2 = __ldg(g_rec + beg + i + 2);
            int4 r3 = __ldg(g_rec + beg + i + 3);
            __half2 q0 = __ldg(g_h2 + r0.x * 32 + lane);
            __half2 q1 = __ldg(g_h2 + r1.x * 32 + lane);
            __half2 q2 = __ldg(g_h2 + r2.x * 32 + lane);
            __half2 q3 = __ldg(g_h2 + r3.x * 32 + lane);
            __half2 hw0 = bits_h2((unsigned)((h < 2) ? r0.y : r0.z));
            __half2 hw1 = bits_h2((unsigned)((h < 2) ? r1.y : r1.z));
            __half2 hw2 = bits_h2((unsigned)((h < 2) ? r2.y : r2.z));
            __half2 hw3 = bits_h2((unsigned)((h < 2) ? r3.y : r3.z));
            float w0 = (h & 1) ? __high2float(hw0) : __low2float(hw0);
            float w1 = (h & 1) ? __high2float(hw1) : __low2float(hw1);
            float w2 = (h & 1) ? __high2float(hw2) : __low2float(hw2);
            float w3 = (h & 1) ? __high2float(hw3) : __low2float(hw3);
            float2 f0 = __half22float2(q0), f1 = __half22float2(q1);
            float2 f2 = __half22float2(q2), f3 = __half22float2(q3);
            acc0 += w0 * f0.x + w1 * f1.x + w2 * f2.x + w3 * f3.x;
            acc1 += w0 * f0.y + w1 * f1.y + w2 * f2.y + w3 * f3.y;
            dn   += w0 + w1 + w2 + w3;
        }
        for (; i < cnt; i++) {
            int4 r0 = __ldg(g_rec + beg + i);
            __half2 q0 = __ldg(g_h2 + r0.x * 32 + lane);
            __half2 hw0 = bits_h2((unsigned)((h < 2) ? r0.y : r0.z));
            float w0 = (h & 1) ? __high2float(hw0) : __low2float(hw0);
            float2 f0 = __half22float2(q0);
            acc0 += w0 * f0.x;
            acc1 += w0 * f0.y;
            dn   += w0;
        }
    }

    if (half == 1) {
        s_part[nb][lane][0] = acc0;
        s_part[nb][lane][1] = acc1;
        s_part[nb][lane][2] = dn;
    }
    __syncthreads();
    if (half == 0 && n < N) {
        acc0 += s_part[nb][lane][0];
        acc1 += s_part[nb][lane][1];
        dn   += s_part[nb][lane][2];

        // self loop (fp16 h)
        float sl = ((const float*)g_asrc4)[n * 4 + h] + ((const float*)g_adst4)[n * 4 + h] + g_vsum[h];
        float es = __expf(lrelu(sl));
        float2 hn = __half22float2(g_h2[n * 32 + lane]);
        float r = 1.f / (dn + es);
        float2 bv = reinterpret_cast<const float2*>(bias)[lane];
        float o0 = (acc0 + es * hn.x) * r + bv.x;
        float o1 = (acc1 + es * hn.y) * r + bv.y;
        reinterpret_cast<float2*>(out + n * 64)[lane] = make_float2(o0, o1);
    }
}

// ---------------- launch ---------------------------------------------------
extern "C" void kernel_launch(void* const* d_in, const int* in_sizes, int n_in,
                              void* d_out, int out_size) {
    const float* x        = (const float*)d_in[0];
    const int*   ei       = (const int*)d_in[1];
    const float* ea       = (const float*)d_in[2];
    const float* W        = (const float*)d_in[3];
    const float* att_src  = (const float*)d_in[4];
    const float* att_dst  = (const float*)d_in[5];
    const float* W_edge   = (const float*)d_in[6];
    const float* att_edge = (const float*)d_in[7];
    const float* bias     = (const float*)d_in[8];
    float* out = (float*)d_out;

    int N = in_sizes[0] / 128;
    int E = in_sizes[1] / 2;
    int nscan = (N + SCAN_CHUNK - 1) / SCAN_CHUNK;

    const int gemm_smem = (8192 + 64 * 132) * 4;

    static cudaStream_t sB = nullptr;
    static cudaEvent_t evF = nullptr, evJ = nullptr;
    if (!sB) {
        cudaFuncSetAttribute(k_gemm, cudaFuncAttributeMaxDynamicSharedMemorySize, gemm_smem);
        cudaStreamCreateWithFlags(&sB, cudaStreamNonBlocking);
        cudaEventCreateWithFlags(&evF, cudaEventDisableTiming);
        cudaEventCreateWithFlags(&evJ, cudaEventDisableTiming);
    }

    cudaEventRecord(evF, 0);
    cudaStreamWaitEvent(sB, evF, 0);

    // chain B: CSR build
    k_prep<<<(N + 255) / 256, 256, 0, sB>>>(W_edge, att_edge, N);
    k_hist<<<(E + 2047) / 2048, 256, 0, sB>>>(ei, E);
    k_scan1<<<nscan, SCAN_CHUNK, 0, sB>>>(N);
    k_scan2<<<1, 256, 0, sB>>>(nscan);
    k_scan3<<<nscan, SCAN_CHUNK, 0, sB>>>(N);

    // chain A: gemm (+fused att dots)
    k_gemm<<<(N + 63) / 64, 256, gemm_smem>>>(x, W, att_src, att_dst, N);

    cudaEventRecord(evJ, sB);
    cudaStreamWaitEvent(0, evJ, 0);

    k_edge<<<(E + 511) / 512, 256>>>(ei, (const float4*)ea, E);
    k_agg<<<(N + 3) / 4, 256>>>(bias, out, N);
}

// round 9
// speedup vs baseline: 1.0772x; 1.0772x over previous
#include <cuda_runtime.h>
#include <cuda_fp16.h>
#include <stdint.h>

#define NMAX 50000
#define EMAX 1600000
#define SCAN_CHUNK 512

// ---------------- scratch (device globals; no allocation) ----------------
__device__ float4  g_h4[NMAX * 16];       // h [N,64] fp32 (self-loop term)
__device__ __half2 g_h2[NMAX * 32];       // h [N,64] fp16 (agg gather)
__device__ float4  g_asrc4[NMAX];         // a_src [N,4]
__device__ float4  g_adst4[NMAX];         // a_dst [N,4]
__device__ float   g_v[64];               // v [16,4]  (d*4+h)
__device__ float   g_vsum[4];
__device__ int     g_cnt[NMAX];           // in-degree
__device__ int     g_off[NMAX];           // CSR offsets
__device__ int     g_cur[NMAX];           // write cursors
__device__ int     g_bsum[256];           // scan block sums
__device__ int     g_src_s[EMAX];         // dst-sorted src ids
struct __align__(8) Ex4 { __half2 a, b; };
__device__ Ex4     g_exs[EMAX];           // dst-sorted exp(logit), 4 heads fp16

__device__ __forceinline__ float lrelu(float a) { return a > 0.f ? a : 0.2f * a; }

__device__ __forceinline__ unsigned h2_bits(__half2 v) {
    union { __half2 h; unsigned u; } cvt; cvt.h = v; return cvt.u;
}
__device__ __forceinline__ __half2 bits_h2(unsigned u) {
    union { unsigned u; __half2 h; } cvt; cvt.u = u; return cvt.h;
}

// ---------------- K1 (stream B): zero g_cnt; block 0 computes v/vsum -----
__global__ void k_prep(const float* __restrict__ We, const float* __restrict__ ae, int N) {
    __shared__ float sv[64];
    int g = blockIdx.x * blockDim.x + threadIdx.x;
    if (g < N) g_cnt[g] = 0;
    if (blockIdx.x == 0) {
        int t = threadIdx.x;
        if (t < 64) {
            int d = t >> 2, h = t & 3;
            float s = 0.f;
#pragma unroll
            for (int c = 0; c < 16; c++) s += We[d * 64 + h * 16 + c] * ae[h * 16 + c];
            sv[t] = s;
            g_v[t] = s;
        }
        __syncthreads();
        if (t < 4) {
            float ss = 0.f;
#pragma unroll
            for (int dd = 0; dd < 16; dd++) ss += sv[dd * 4 + t];
            g_vsum[t] = ss;
        }
    }
}

// ---------------- K2 (stream B): in-degree histogram, 8 edges/thread ------
__global__ void k_hist(const int* __restrict__ ei, int E) {
    int base = (blockIdx.x * blockDim.x + threadIdx.x) * 8;
    if (base >= E) return;
    const int* d = ei + E;
    if (base + 8 <= E && ((E & 3) == 0)) {
        int4 a = *reinterpret_cast<const int4*>(d + base);
        int4 b = *reinterpret_cast<const int4*>(d + base + 4);
        atomicAdd(&g_cnt[a.x], 1); atomicAdd(&g_cnt[a.y], 1);
        atomicAdd(&g_cnt[a.z], 1); atomicAdd(&g_cnt[a.w], 1);
        atomicAdd(&g_cnt[b.x], 1); atomicAdd(&g_cnt[b.y], 1);
        atomicAdd(&g_cnt[b.z], 1); atomicAdd(&g_cnt[b.w], 1);
    } else {
        for (int i = base; i < E && i < base + 8; i++) atomicAdd(&g_cnt[d[i]], 1);
    }
}

// ---------------- K3-5 (stream B): exclusive scan -> g_off / g_cur --------
__global__ void k_scan1(int N) {
    __shared__ int s[SCAN_CHUNK];
    int g = blockIdx.x * SCAN_CHUNK + threadIdx.x;
    int v = (g < N) ? g_cnt[g] : 0;
    s[threadIdx.x] = v;
    __syncthreads();
    for (int d = 1; d < SCAN_CHUNK; d <<= 1) {
        int tv = (threadIdx.x >= d) ? s[threadIdx.x - d] : 0;
        __syncthreads();
        s[threadIdx.x] += tv;
        __syncthreads();
    }
    if (g < N) g_off[g] = s[threadIdx.x] - v;
    if (threadIdx.x == SCAN_CHUNK - 1) g_bsum[blockIdx.x] = s[SCAN_CHUNK - 1];
}

__global__ void k_scan2(int nb) {
    __shared__ int s[256];
    int v = (threadIdx.x < nb) ? g_bsum[threadIdx.x] : 0;
    s[threadIdx.x] = v;
    __syncthreads();
    for (int d = 1; d < 256; d <<= 1) {
        int tv = (threadIdx.x >= d) ? s[threadIdx.x - d] : 0;
        __syncthreads();
        s[threadIdx.x] += tv;
        __syncthreads();
    }
    if (threadIdx.x < nb) g_bsum[threadIdx.x] = s[threadIdx.x] - v;
}

__global__ void k_scan3(int N) {
    int g = blockIdx.x * SCAN_CHUNK + threadIdx.x;
    if (g < N) {
        int o = g_off[g] + g_bsum[blockIdx.x];
        g_off[g] = o;
        g_cur[g] = o;
    }
}

// ---------------- K6 (stream A): h = x @ W, fused a_src/a_dst epilogue ----
__global__ void k_gemm(const float* __restrict__ x, const float* __restrict__ W,
                       const float* __restrict__ att_src, const float* __restrict__ att_dst,
                       int N) {
    extern __shared__ float smem[];
    float* sW = smem;             // 8192 floats
    float* sx = smem + 8192;      // 64*132 floats
    int t = threadIdx.x;
    int n0 = blockIdx.x * 64;

    for (int i = t; i < 2048; i += 256)
        reinterpret_cast<float4*>(sW)[i] = reinterpret_cast<const float4*>(W)[i];

    for (int i = t; i < 2048; i += 256) {
        int row = i >> 5;
        int col4 = i & 31;
        float4 v = make_float4(0.f, 0.f, 0.f, 0.f);
        if (n0 + row < N)
            v = reinterpret_cast<const float4*>(x)[(size_t)(n0 + row) * 32 + col4];
        float* dp = sx + row * 132 + col4 * 4;
        dp[0] = v.x; dp[1] = v.y; dp[2] = v.z; dp[3] = v.w;
    }
    __syncthreads();

    int tc = t & 15;          // channel group (4 channels)
    int tn = t >> 4;          // node group (4 nodes)
    const float* xr = sx + (tn * 4) * 132;
    float acc[4][4];
#pragma unroll
    for (int i = 0; i < 4; i++)
#pragma unroll
        for (int j = 0; j < 4; j++) acc[i][j] = 0.f;

#pragma unroll 4
    for (int k = 0; k < 128; k++) {
        float4 wv = *reinterpret_cast<const float4*>(sW + k * 64 + tc * 4);
        float x0 = xr[k], x1 = xr[132 + k], x2 = xr[264 + k], x3 = xr[396 + k];
        acc[0][0] += x0 * wv.x; acc[0][1] += x0 * wv.y; acc[0][2] += x0 * wv.z; acc[0][3] += x0 * wv.w;
        acc[1][0] += x1 * wv.x; acc[1][1] += x1 * wv.y; acc[1][2] += x1 * wv.z; acc[1][3] += x1 * wv.w;
        acc[2][0] += x2 * wv.x; acc[2][1] += x2 * wv.y; acc[2][2] += x2 * wv.z; acc[2][3] += x2 * wv.w;
        acc[3][0] += x3 * wv.x; acc[3][1] += x3 * wv.y; acc[3][2] += x3 * wv.z; acc[3][3] += x3 * wv.w;
    }

    // store h fp32 + fp16 copy
#pragma unroll
    for (int i = 0; i < 4; i++) {
        int n = n0 + tn * 4 + i;
        if (n < N) {
            reinterpret_cast<float4*>((float*)g_h4 + n * 64)[tc] =
                make_float4(acc[i][0], acc[i][1], acc[i][2], acc[i][3]);
            __half2 p0 = __floats2half2_rn(acc[i][0], acc[i][1]);
            __half2 p1 = __floats2half2_rn(acc[i][2], acc[i][3]);
            *reinterpret_cast<uint2*>(g_h2 + n * 32 + tc * 2) =
                make_uint2(h2_bits(p0), h2_bits(p1));
        }
    }

    // fused a_src/a_dst: dot over 4 channels, reduce across 4-lane head group
    float4 asv = *reinterpret_cast<const float4*>(att_src + tc * 4);
    float4 adv = *reinterpret_cast<const float4*>(att_dst + tc * 4);
#pragma unroll
    for (int i = 0; i < 4; i++) {
        float ps = acc[i][0] * asv.x + acc[i][1] * asv.y + acc[i][2] * asv.z + acc[i][3] * asv.w;
        float pd = acc[i][0] * adv.x + acc[i][1] * adv.y + acc[i][2] * adv.z + acc[i][3] * adv.w;
        ps += __shfl_xor_sync(0xffffffffu, ps, 1);
        ps += __shfl_xor_sync(0xffffffffu, ps, 2);
        pd += __shfl_xor_sync(0xffffffffu, pd, 1);
        pd += __shfl_xor_sync(0xffffffffu, pd, 2);
        int n = n0 + tn * 4 + i;
        if ((tc & 3) == 0 && n < N) {
            int head = tc >> 2;
            ((float*)g_asrc4)[n * 4 + head] = ps;
            ((float*)g_adst4)[n * 4 + head] = pd;
        }
    }
}

// ---------------- K7 (joined): per-edge exp(lrelu(logit)) + CSR permute ---
__global__ void k_edge(const int* __restrict__ ei, const float4* __restrict__ ea4, int E) {
    __shared__ float sv[64];
    if (threadIdx.x < 64) sv[threadIdx.x] = g_v[threadIdx.x];
    __syncthreads();
    int e = blockIdx.x * blockDim.x + threadIdx.x;
    if (e >= E) return;
    int src = ei[e], dst = ei[E + e];
    float a0 = 0.f, a1 = 0.f, a2 = 0.f, a3 = 0.f;
#pragma unroll
    for (int k = 0; k < 4; k++) {
        float4 q = __ldcs(ea4 + e * 4 + k);   // stream, evict-first
        const float* vp = sv + k * 16;
        a0 += q.x * vp[0] + q.y * vp[4] + q.z * vp[8]  + q.w * vp[12];
        a1 += q.x * vp[1] + q.y * vp[5] + q.z * vp[9]  + q.w * vp[13];
        a2 += q.x * vp[2] + q.y * vp[6] + q.z * vp[10] + q.w * vp[14];
        a3 += q.x * vp[3] + q.y * vp[7] + q.z * vp[11] + q.w * vp[15];
    }
    float4 as = g_asrc4[src];
    float4 ad = g_adst4[dst];
    Ex4 ex;
    ex.a = __floats2half2_rn(__expf(lrelu(as.x + ad.x + a0)),
                             __expf(lrelu(as.y + ad.y + a1)));
    ex.b = __floats2half2_rn(__expf(lrelu(as.z + ad.z + a2)),
                             __expf(lrelu(as.w + ad.w + a3)));
    int pos = atomicAdd(&g_cur[dst], 1);
    g_src_s[pos] = src;
    g_exs[pos] = ex;
}

// ---------------- K8: per-node aggregation, vectorized record loads -------
// one warp per node; lane owns channels {2*lane, 2*lane+1}, head = lane>>3
__global__ void k_agg(const float* __restrict__ bias, float* __restrict__ out, int N) {
    int n = (blockIdx.x * blockDim.x + threadIdx.x) >> 5;
    int lane = threadIdx.x & 31;
    if (n >= N) return;
    int off = g_off[n];
    int end = off + g_cnt[n];
    int h = lane >> 3;
    bool hi_head = (h >= 2);
    bool hi_half = (h & 1);

    float acc0 = 0.f, acc1 = 0.f, dn = 0.f;

    // peel to 4-edge alignment (g_src_s 16B-aligned, g_exs 32B-aligned there)
    int i = off;
    int aligned = (off + 3) & ~3;
    for (; i < end && i < aligned; i++) {
        int s0 = __ldg(g_src_s + i);
        Ex4 e0 = g_exs[i];
        __half2 hw = hi_head ? e0.b : e0.a;
        float w = hi_half ? __high2float(hw) : __low2float(hw);
        float2 f = __half22float2(__ldg(g_h2 + s0 * 32 + lane));
        acc0 += w * f.x; acc1 += w * f.y; dn += w;
    }

    // main: 4 edges per iteration, 7 LDG instead of 12
    for (; i + 4 <= end; i += 4) {
        int4 s4 = __ldg(reinterpret_cast<const int4*>(g_src_s + i));
        float4 ex01 = __ldg(reinterpret_cast<const float4*>(g_exs + i));      // edges i, i+1
        float4 ex23 = __ldg(reinterpret_cast<const float4*>(g_exs + i + 2));  // edges i+2, i+3
        __half2 q0 = __ldg(g_h2 + s4.x * 32 + lane);
        __half2 q1 = __ldg(g_h2 + s4.y * 32 + lane);
        __half2 q2 = __ldg(g_h2 + s4.z * 32 + lane);
        __half2 q3 = __ldg(g_h2 + s4.w * 32 + lane);
        __half2 hw0 = bits_h2(__float_as_uint(hi_head ? ex01.y : ex01.x));
        __half2 hw1 = bits_h2(__float_as_uint(hi_head ? ex01.w : ex01.z));
        __half2 hw2 = bits_h2(__float_as_uint(hi_head ? ex23.y : ex23.x));
        __half2 hw3 = bits_h2(__float_as_uint(hi_head ? ex23.w : ex23.z));
        float w0 = hi_half ? __high2float(hw0) : __low2float(hw0);
        float w1 = hi_half ? __high2float(hw1) : __low2float(hw1);
        float w2 = hi_half ? __high2float(hw2) : __low2float(hw2);
        float w3 = hi_half ? __high2float(hw3) : __low2float(hw3);
        float2 f0 = __half22float2(q0), f1 = __half22float2(q1);
        float2 f2 = __half22float2(q2), f3 = __half22float2(q3);
        acc0 += w0 * f0.x + w1 * f1.x + w2 * f2.x + w3 * f3.x;
        acc1 += w0 * f0.y + w1 * f1.y + w2 * f2.y + w3 * f3.y;
        dn   += w0 + w1 + w2 + w3;
    }

    // tail
    for (; i < end; i++) {
        int s0 = __ldg(g_src_s + i);
        Ex4 e0 = g_exs[i];
        __half2 hw = hi_head ? e0.b : e0.a;
        float w = hi_half ? __high2float(hw) : __low2float(hw);
        float2 f = __half22float2(__ldg(g_h2 + s0 * 32 + lane));
        acc0 += w * f.x; acc1 += w * f.y; dn += w;
    }

    // self loop (fp32 h)
    float sl = ((const float*)g_asrc4)[n * 4 + h] + ((const float*)g_adst4)[n * 4 + h] + g_vsum[h];
    float es = __expf(lrelu(sl));
    const float* hn = (const float*)g_h4 + n * 64;
    float r = 1.f / (dn + es);
    float2 bv = reinterpret_cast<const float2*>(bias)[lane];
    float o0 = (acc0 + es * hn[2 * lane])     * r + bv.x;
    float o1 = (acc1 + es * hn[2 * lane + 1]) * r + bv.y;
    reinterpret_cast<float2*>(out + n * 64)[lane] = make_float2(o0, o1);
}

// ---------------- launch ---------------------------------------------------
extern "C" void kernel_launch(void* const* d_in, const int* in_sizes, int n_in,
                              void* d_out, int out_size) {
    const float* x        = (const float*)d_in[0];
    const int*   ei       = (const int*)d_in[1];
    const float* ea       = (const float*)d_in[2];
    const float* W        = (const float*)d_in[3];
    const float* att_src  = (const float*)d_in[4];
    const float* att_dst  = (const float*)d_in[5];
    const float* W_edge   = (const float*)d_in[6];
    const float* att_edge = (const float*)d_in[7];
    const float* bias     = (const float*)d_in[8];
    float* out = (float*)d_out;

    int N = in_sizes[0] / 128;
    int E = in_sizes[1] / 2;
    int nscan = (N + SCAN_CHUNK - 1) / SCAN_CHUNK;

    const int gemm_smem = (8192 + 64 * 132) * 4;

    static cudaStream_t sB = nullptr;
    static cudaEvent_t evF = nullptr, evJ = nullptr;
    if (!sB) {
        cudaFuncSetAttribute(k_gemm, cudaFuncAttributeMaxDynamicSharedMemorySize, gemm_smem);
        cudaStreamCreateWithFlags(&sB, cudaStreamNonBlocking);
        cudaEventCreateWithFlags(&evF, cudaEventDisableTiming);
        cudaEventCreateWithFlags(&evJ, cudaEventDisableTiming);
    }

    cudaEventRecord(evF, 0);
    cudaStreamWaitEvent(sB, evF, 0);

    // chain B: CSR build
    k_prep<<<(N + 255) / 256, 256, 0, sB>>>(W_edge, att_edge, N);
    k_hist<<<(E + 2047) / 2048, 256, 0, sB>>>(ei, E);
    k_scan1<<<nscan, SCAN_CHUNK, 0, sB>>>(N);
    k_scan2<<<1, 256, 0, sB>>>(nscan);
    k_scan3<<<nscan, SCAN_CHUNK, 0, sB>>>(N);

    // chain A: gemm (+fused att dots)
    k_gemm<<<(N + 63) / 64, 256, gemm_smem>>>(x, W, att_src, att_dst, N);

    cudaEventRecord(evJ, sB);
    cudaStreamWaitEvent(0, evJ, 0);

    k_edge<<<(E + 255) / 256, 256>>>(ei, (const float4*)ea, E);
    k_agg<<<(N * 32 + 255) / 256, 256>>>(bias, out, N);
}